// round 4
// baseline (speedup 1.0000x reference)
#include <cuda_runtime.h>
#include <cuda_bf16.h>

// MergedEmbeddingBag: weights [T,N,D] f32, indices [T,TOTAL] i32, offsets [T,B] i32
// out [T,B,D] f32, sum pooling. T=8, N=100000, D=128, B=16384, L=20.
//
// R4: warp-per-8-bags, software-pipelined index prefetch.
//  - One coalesced 9-int offset read per warp gives all 8 bag boundaries (shfl).
//  - While gathering bag b, bag b+1's indices are already loading (prefetch),
//    removing the per-bag idx-load latency bubble of the one-shot-warp design.
//  - float4 gathers: 512 B/warp, perfectly coalesced; L2 captures all reuse.

#define EB_T 8
#define EB_N 100000
#define EB_D 128
#define EB_B 16384
#define EB_LOG2_B 14
#define BAGS_PER_WARP 8
#define FULLMASK 0xffffffffu

__global__ void __launch_bounds__(256, 4)
merged_embeddingbag_pipe_kernel(const float* __restrict__ weights,
                                const int* __restrict__ indices,
                                const int* __restrict__ offsets,
                                float* __restrict__ out,
                                int total_per_table)
{
    const int gw   = blockIdx.x * (blockDim.x >> 5) + (threadIdx.x >> 5);
    const int lane = threadIdx.x & 31;

    const int base_global = gw * BAGS_PER_WARP;         // first (tbl,bag) flat id
    const int tbl      = base_global >> EB_LOG2_B;      // 8 bags never cross tables
    const int base_bag = base_global & (EB_B - 1);

    const int* off_t = offsets + tbl * EB_B;
    const int* idx_base = indices + (size_t)tbl * total_per_table;
    const float4* __restrict__ w4 =
        (const float4*)(weights + (size_t)tbl * EB_N * EB_D);

    // One coalesced read covers boundaries of all 8 bags: lanes 0..8.
    int off_val = 0;
    if (lane <= BAGS_PER_WARP) {
        const int bo = base_bag + lane;
        off_val = (bo < EB_B) ? __ldg(&off_t[bo]) : total_per_table;
    }

    // Prologue: indices for bag 0.
    int start0 = __shfl_sync(FULLMASK, off_val, 0);
    int end0   = __shfl_sync(FULLMASK, off_val, 1);
    int cnt    = end0 - start0; if (cnt < 0) cnt = 0;
    int cur_idx = (lane < cnt) ? __ldg(&idx_base[start0 + lane]) : 0;

    float4* __restrict__ o4 = (float4*)out + (size_t)base_global * 32 + lane;

    #pragma unroll
    for (int b = 0; b < BAGS_PER_WARP; b++) {
        // Prefetch next bag's indices before consuming current ones.
        int next_idx = 0, next_cnt = 0;
        if (b + 1 < BAGS_PER_WARP) {
            const int s = __shfl_sync(FULLMASK, off_val, b + 1);
            const int e = __shfl_sync(FULLMASK, off_val, b + 2);
            next_cnt = e - s; if (next_cnt < 0) next_cnt = 0;
            next_idx = (lane < next_cnt) ? __ldg(&idx_base[s + lane]) : 0;
        }

        float4 acc = make_float4(0.f, 0.f, 0.f, 0.f);
        if (cnt == 20) {
            #pragma unroll
            for (int j = 0; j < 20; j++) {
                const int r = __shfl_sync(FULLMASK, cur_idx, j);
                const float4 v = __ldg(&w4[r * 32 + lane]);
                acc.x += v.x; acc.y += v.y; acc.z += v.z; acc.w += v.w;
            }
        } else {
            // General path (bags larger than one warp-load of indices).
            int done = 0;
            int mycur = cur_idx;
            while (done < cnt) {
                const int m = min(32, cnt - done);
                for (int j = 0; j < m; j++) {
                    const int r = __shfl_sync(FULLMASK, mycur, j);
                    const float4 v = __ldg(&w4[r * 32 + lane]);
                    acc.x += v.x; acc.y += v.y; acc.z += v.z; acc.w += v.w;
                }
                done += m;
                if (done < cnt) {
                    const int s = __shfl_sync(FULLMASK, off_val, b);
                    mycur = (lane < cnt - done) ? __ldg(&idx_base[s + done + lane]) : 0;
                }
            }
        }

        o4[(size_t)b * 32] = acc;
        cur_idx = next_idx;
        cnt     = next_cnt;
    }
}

extern "C" void kernel_launch(void* const* d_in, const int* in_sizes, int n_in,
                              void* d_out, int out_size)
{
    const float* weights = (const float*)d_in[0];
    const int*   indices = (const int*)d_in[1];
    const int*   offsets = (const int*)d_in[2];
    float*       out     = (float*)d_out;

    const int total_per_table = in_sizes[1] / EB_T;   // 327680

    const int warps_per_block = 8;                    // 256 threads
    const int total_warps = (EB_T * EB_B) / BAGS_PER_WARP;  // 16384
    const int nblocks = total_warps / warps_per_block;      // 2048

    merged_embeddingbag_pipe_kernel<<<nblocks, warps_per_block * 32>>>(
        weights, indices, offsets, out, total_per_table);
}